// round 8
// baseline (speedup 1.0000x reference)
#include <cuda_runtime.h>
#include <cstdint>

// x[16,256,128,128] f32, w[512,256,3,3], bias[512], blur_k[4,4] -> y[16,512,64,64]
// R8: CTA 128x256, warp 64x64, all-CP16 B staging via 3rd (shifted-even) plane.
#define WP       68
#define NSTRIDE  8772        // 129*68
#define CSTRIDE  140352      // 16*NSTRIDE
#define PLANE    35930112    // 256*CSTRIDE
#define BPITCH   264         // B smem row pitch (floats)

__device__ __align__(16) float g_xbs[3u * 35930112u];  // planes: even, odd, even-shift1
__device__ __align__(16) float g_apk[4 * 72 * 4096];   // weights, mma-fragment order

// ---------------- helpers ----------------
__device__ __forceinline__ uint32_t smem_u32(const void* p) {
    uint32_t a;
    asm("{ .reg .u64 t; cvta.to.shared.u64 t, %1; cvt.u32.u64 %0, t; }" : "=r"(a) : "l"(p));
    return a;
}
__device__ __forceinline__ float tf32r(float x) {
    uint32_t r; asm("cvt.rna.tf32.f32 %0, %1;" : "=r"(r) : "f"(x));
    return __uint_as_float(r);
}
#define CP16(dst, src) \
    asm volatile("cp.async.cg.shared.global [%0], [%1], 16;" :: "r"(dst), "l"(src))
#define CPCOMMIT() asm volatile("cp.async.commit_group;" ::: "memory")
#define CPWAIT(n)  asm volatile("cp.async.wait_group %0;" :: "n"(n) : "memory")

__device__ __forceinline__ void mma8(float* d, const float4& a, float b0f, float b1f) {
    const uint32_t* ai = reinterpret_cast<const uint32_t*>(&a);
    uint32_t b0 = __float_as_uint(b0f), b1 = __float_as_uint(b1f);
    asm volatile(
        "mma.sync.aligned.m16n8k8.row.col.f32.tf32.tf32.f32 "
        "{%0,%1,%2,%3}, {%4,%5,%6,%7}, {%8,%9}, {%0,%1,%2,%3};"
        : "+f"(d[0]), "+f"(d[1]), "+f"(d[2]), "+f"(d[3])
        : "r"(ai[0]), "r"(ai[1]), "r"(ai[2]), "r"(ai[3]), "r"(b0), "r"(b1));
}

// ---------------- 1. weight prep: scale + tf32-round + mma-fragment permute ----
__global__ __launch_bounds__(256) void prep_kernel(const float* __restrict__ w) {
    int idx = blockIdx.x * 256 + threadIdx.x;       // 512*2304
    if (idx >= 512 * 2304) return;
    int oc = idx / 2304, k = idx - oc * 2304;       // k = tap*256 + c
    int c = k & 255, tap = k >> 8;
    int kh = tap / 3, kw = tap - kh * 3;
    float v = tf32r(w[((oc * 256 + c) * 3 + kh) * 3 + kw] * (1.0f / 48.0f));
    int mt = oc >> 7, m = oc & 127;
    int kt = k >> 5, kl = k & 31;
    int ks = kl >> 3, kc = kl & 7;
    int chi = kc >> 2, c4 = kc & 3;
    int wm = m >> 6, mi = (m >> 4) & 3, mr = m & 15;
    int rhi = mr >> 3, gid = mr & 7;
    int lanei = gid * 4 + c4;
    int comp = chi * 2 + rhi;                       // (r,c),(r+8,c),(r,c+4),(r+8,c+4)
    g_apk[(size_t)(mt * 72 + kt) * 4096 + ((ks * 8 + wm * 4 + mi) * 32 + lanei) * 4 + comp] = v;
}

// ---------------- 2. separable blur -> 3 planes (even, odd, even-shift1) ------
__global__ __launch_bounds__(256) void blur_kernel(const float* __restrict__ x,
                                                   const float* __restrict__ bk) {
    __shared__ float s[37 * 140];
    int tid = threadIdx.x, bid = blockIdx.x;        // 16384 CTAs
    int hb = bid & 3, n = (bid >> 2) & 15, c = bid >> 6;
    int h0 = hb * 33;
    const float* xp = x + (size_t)(n * 256 + c) * 16384;
#pragma unroll
    for (int i = 0; i < 6; ++i) {
        int idx = tid + i * 256;
        if (idx < 37 * 35) {
            int rr = idx / 35, c4 = idx - rr * 35;
            int ih = h0 - 2 + rr;
            float4 v = make_float4(0.f, 0.f, 0.f, 0.f);
            if (ih >= 0 && ih < 128 && c4 < 32)
                v = *reinterpret_cast<const float4*>(xp + ih * 128 + c4 * 4);
            *reinterpret_cast<float4*>(&s[rr * 140 + c4 * 4]) = v;
        }
    }
    // K = u u^T exactly (rank-1): u_b = column sums; row factor v = u (K.sum()=64 norm).
    float u0 = __ldg(bk + 0) + __ldg(bk + 4) + __ldg(bk + 8)  + __ldg(bk + 12);
    float u1 = __ldg(bk + 1) + __ldg(bk + 5) + __ldg(bk + 9)  + __ldg(bk + 13);
    float u2 = __ldg(bk + 2) + __ldg(bk + 6) + __ldg(bk + 10) + __ldg(bk + 14);
    float u3 = __ldg(bk + 3) + __ldg(bk + 7) + __ldg(bk + 11) + __ldg(bk + 15);
    __syncthreads();
#pragma unroll 1
    for (int t = tid; t < 561; t += 256) {          // 17 h-pairs x 33 w-quads
        int ph = t / 33, wq = t - ph * 33;
        int par = (wq >= 17) ? 1 : 0;
        int qw = par ? (wq - 17) : wq;
        int h0p = ph * 2;
        int basew = qw * 8 + par;                   // w' = basew + 2j (same parity)
        float hv[5][4];
#pragma unroll
        for (int dr = 0; dr < 5; ++dr) {
            const float* row = s + (h0p + dr) * 140;
            float xv[10];
#pragma unroll
            for (int q = 0; q < 10; ++q) {
                int iw = basew - 2 + q;
                xv[q] = (iw >= 0) ? row[iw] : 0.0f; // cols >=128 are zero-padded
            }
#pragma unroll
            for (int jj = 0; jj < 4; ++jj)
                hv[dr][jj] = u0 * xv[2 * jj] + u1 * xv[2 * jj + 1]
                           + u2 * xv[2 * jj + 2] + u3 * xv[2 * jj + 3];
        }
#pragma unroll
        for (int hh = 0; hh < 2; ++hh) {
            int hp = h0p + hh, habs = h0 + hp;
            if (hp > 32 || habs > 128) continue;
            float o[4];
#pragma unroll
            for (int jj = 0; jj < 4; ++jj)
                o[jj] = tf32r(u0 * hv[hh][jj] + u1 * hv[hh + 1][jj]
                            + u2 * hv[hh + 2][jj] + u3 * hv[hh + 3][jj]);
            size_t rowoff = (size_t)c * CSTRIDE + (size_t)n * NSTRIDE + (size_t)habs * WP;
            float* dst = g_xbs + (size_t)par * PLANE + rowoff + qw * 4;
            if (par == 0) {
                float* p2 = g_xbs + 2u * (size_t)PLANE + rowoff;   // plane2[i] = even[i+1]
                if (qw == 16) {
                    dst[0] = o[0];                  // even col 64 (w'=128)
                    p2[63] = o[0];
                } else {
                    *reinterpret_cast<float4*>(dst) = make_float4(o[0], o[1], o[2], o[3]);
#pragma unroll
                    for (int jj = 0; jj < 4; ++jj) {
                        int i2 = qw * 4 + jj - 1;
                        if (i2 >= 0) p2[i2] = o[jj];
                    }
                }
            } else {
                *reinterpret_cast<float4*>(dst) = make_float4(o[0], o[1], o[2], o[3]);
            }
        }
    }
}

// ---------------- 3. implicit GEMM: CTA 128x256, warp 64x64, K-tile 32 --------
#define STG_STRIDE 50176u    // 16384 (A) + 33792 (B: 32 x 264 floats)

__device__ __forceinline__ void load_stage(uint32_t sbase, int kt, int tid, int mt,
                                           int n_img, int ohbase) {
    // A: flat copy of 16KB fragment-ordered tile
    const float* asrc = g_apk + (size_t)(mt * 72 + kt) * 4096;
#pragma unroll
    for (int i = 0; i < 4; ++i)
        CP16(sbase + (uint32_t)(tid + 256 * i) * 16u, asrc + (tid + 256 * i) * 4);
    // B: 32 k-rows x 256 j; plane index = kw (all 16B-aligned)
    int tap = kt >> 3, ct = kt & 7;
    int kh = tap / 3, kw = tap - kh * 3;
    int r = tid & 31, q = tid >> 5;                 // k-row, 32-col block
    int j0 = q * 32;
    int oh = ohbase + (j0 >> 6), ow = j0 & 63;      // 32-block lies in one oh row
    const float* src = g_xbs + (size_t)kw * PLANE + (size_t)(ct * 32 + r) * CSTRIDE
                     + (size_t)n_img * NSTRIDE + (size_t)(2 * oh + kh) * WP + ow;
    uint32_t sB = sbase + 16384u + (uint32_t)(r * BPITCH + j0) * 4u;
#pragma unroll
    for (int i = 0; i < 8; ++i)
        CP16(sB + (uint32_t)(i * 16), src + i * 4);
}

__device__ __forceinline__ void mma_stage(const char* base, int lane, int wm, int wn,
                                          float acc[4][8][4]) {
    const float4* sA4 = reinterpret_cast<const float4*>(base);
    const float*  sB  = reinterpret_cast<const float*>(base + 16384);
    int r = lane & 3, gid = lane >> 2;
#pragma unroll
    for (int ks = 0; ks < 4; ++ks) {
        float4 af[4];
#pragma unroll
        for (int mi = 0; mi < 4; ++mi)
            af[mi] = sA4[(ks * 8 + wm * 4 + mi) * 32 + lane];
        float b0[8], b1[8];
#pragma unroll
        for (int ni = 0; ni < 8; ++ni) {
            int nn = wn * 64 + ni * 8 + gid;
            b0[ni] = sB[(ks * 8 + r) * BPITCH + nn];
            b1[ni] = sB[(ks * 8 + 4 + r) * BPITCH + nn];
        }
#pragma unroll
        for (int mi = 0; mi < 4; ++mi)
#pragma unroll
            for (int ni = 0; ni < 8; ++ni)
                mma8(acc[mi][ni], af[mi], b0[ni], b1[ni]);
    }
}

__global__ __launch_bounds__(256, 1) void gemm_kernel(const float* __restrict__ bias,
                                                      float* __restrict__ out) {
    extern __shared__ char smem[];
    uint32_t sbu = smem_u32(smem);
    const int tid = threadIdx.x, lane = tid & 31, wid = tid >> 5;
    const int wm = wid >> 2, wn = wid & 3;          // 2 x 4 warp grid, 64x64 tiles
    const int bid = blockIdx.x;                     // 1024 CTAs
    const int mt = bid & 3, nt = bid >> 2;          // nt 0..255
    const int n_img = nt >> 4, ohbase = (nt & 15) << 2;

    float acc[4][8][4];
#pragma unroll
    for (int a = 0; a < 4; ++a)
#pragma unroll
        for (int b = 0; b < 8; ++b)
#pragma unroll
            for (int qq = 0; qq < 4; ++qq) acc[a][b][qq] = 0.0f;

    load_stage(sbu, 0, tid, mt, n_img, ohbase);               CPCOMMIT();
    load_stage(sbu + STG_STRIDE, 1, tid, mt, n_img, ohbase);  CPCOMMIT();

#pragma unroll 1
    for (int kt = 0; kt < 72; ++kt) {
        CPWAIT(1);
        __syncthreads();
        if (kt + 2 < 72)
            load_stage(sbu + (uint32_t)((kt + 2) % 3) * STG_STRIDE, kt + 2,
                       tid, mt, n_img, ohbase);
        CPCOMMIT();
        mma_stage(smem + (size_t)(kt % 3) * STG_STRIDE, lane, wm, wn, acc);
    }

    // epilogue: D frags -> +bias -> float2 stores (coalesced 256B runs per row)
#pragma unroll
    for (int mi = 0; mi < 4; ++mi) {
        int m = wm * 64 + mi * 16 + (lane >> 2);
        float blo = __ldg(bias + mt * 128 + m);
        float bhi = __ldg(bias + mt * 128 + m + 8);
#pragma unroll
        for (int ni = 0; ni < 8; ++ni) {
            int jj = wn * 64 + ni * 8 + (lane & 3) * 2;
            int oh = ohbase + (jj >> 6), ow = jj & 63;
            size_t base = (((size_t)n_img * 512 + mt * 128 + m) * 64 + oh) * 64 + ow;
            *reinterpret_cast<float2*>(out + base) =
                make_float2(acc[mi][ni][0] + blo, acc[mi][ni][1] + blo);
            *reinterpret_cast<float2*>(out + base + 8 * 4096) =
                make_float2(acc[mi][ni][2] + bhi, acc[mi][ni][3] + bhi);
        }
    }
}

// ---------------- launch ----------------
extern "C" void kernel_launch(void* const* d_in, const int* in_sizes, int n_in,
                              void* d_out, int out_size) {
    const float* x    = (const float*)d_in[0];
    const float* w    = (const float*)d_in[1];
    const float* bias = (const float*)d_in[2];
    const float* bk   = (const float*)d_in[3];
    float* out = (float*)d_out;
    (void)in_sizes; (void)n_in; (void)out_size;

    cudaFuncSetAttribute(gemm_kernel, cudaFuncAttributeMaxDynamicSharedMemorySize, 150528);

    prep_kernel<<<4608, 256>>>(w);
    blur_kernel<<<16384, 256>>>(x, bk);
    gemm_kernel<<<1024, 256, 150528>>>(bias, out);
}

// round 9
// speedup vs baseline: 1.0659x; 1.0659x over previous
#include <cuda_runtime.h>
#include <cstdint>

// x[16,256,128,128] f32, w[512,256,3,3], bias[512], blur_k[4,4] -> y[16,512,64,64]
// R9: R7 tiling (CTA 128x128, warp 64x32, 2 CTA/SM) + all-CP16 B staging via 3 planes.
#define WP       68
#define NSTRIDE  8772        // 129*68
#define CSTRIDE  140352      // 16*NSTRIDE
#define PLANE    35930112    // 256*CSTRIDE
#define BPITCH   136         // B smem row pitch (floats)

__device__ __align__(16) float g_xbs[3u * 35930112u];  // planes: even, odd, even-shift1
__device__ __align__(16) float g_apk[4 * 72 * 4096];   // weights, mma-fragment order

// ---------------- helpers ----------------
__device__ __forceinline__ uint32_t smem_u32(const void* p) {
    uint32_t a;
    asm("{ .reg .u64 t; cvta.to.shared.u64 t, %1; cvt.u32.u64 %0, t; }" : "=r"(a) : "l"(p));
    return a;
}
__device__ __forceinline__ float tf32r(float x) {
    uint32_t r; asm("cvt.rna.tf32.f32 %0, %1;" : "=r"(r) : "f"(x));
    return __uint_as_float(r);
}
#define CP16(dst, src) \
    asm volatile("cp.async.cg.shared.global [%0], [%1], 16;" :: "r"(dst), "l"(src))
#define CPCOMMIT() asm volatile("cp.async.commit_group;" ::: "memory")
#define CPWAIT(n)  asm volatile("cp.async.wait_group %0;" :: "n"(n) : "memory")

__device__ __forceinline__ void mma8(float* d, const float4& a, float b0f, float b1f) {
    const uint32_t* ai = reinterpret_cast<const uint32_t*>(&a);
    uint32_t b0 = __float_as_uint(b0f), b1 = __float_as_uint(b1f);
    asm volatile(
        "mma.sync.aligned.m16n8k8.row.col.f32.tf32.tf32.f32 "
        "{%0,%1,%2,%3}, {%4,%5,%6,%7}, {%8,%9}, {%0,%1,%2,%3};"
        : "+f"(d[0]), "+f"(d[1]), "+f"(d[2]), "+f"(d[3])
        : "r"(ai[0]), "r"(ai[1]), "r"(ai[2]), "r"(ai[3]), "r"(b0), "r"(b1));
}

// ---------------- 1. weight prep: scale + tf32-round + mma-fragment permute ----
__global__ __launch_bounds__(256) void prep_kernel(const float* __restrict__ w) {
    int idx = blockIdx.x * 256 + threadIdx.x;       // 512*2304
    if (idx >= 512 * 2304) return;
    int oc = idx / 2304, k = idx - oc * 2304;       // k = tap*256 + c
    int c = k & 255, tap = k >> 8;
    int kh = tap / 3, kw = tap - kh * 3;
    float v = tf32r(w[((oc * 256 + c) * 3 + kh) * 3 + kw] * (1.0f / 48.0f));
    int mt = oc >> 7, m = oc & 127;
    int kt = k >> 5, kl = k & 31;
    int ks = kl >> 3, kc = kl & 7;
    int chi = kc >> 2, c4 = kc & 3;
    int wm = m >> 6, mi = (m >> 4) & 3, mr = m & 15;
    int rhi = mr >> 3, gid = mr & 7;
    int lanei = gid * 4 + c4;
    int comp = chi * 2 + rhi;                       // (r,c),(r+8,c),(r,c+4),(r+8,c+4)
    g_apk[(size_t)(mt * 72 + kt) * 4096 + ((ks * 8 + wm * 4 + mi) * 32 + lanei) * 4 + comp] = v;
}

// ---------------- 2. separable blur -> 3 planes (even, odd, even-shift1) ------
__global__ __launch_bounds__(256) void blur_kernel(const float* __restrict__ x,
                                                   const float* __restrict__ bk) {
    __shared__ float s[37 * 140];
    int tid = threadIdx.x, bid = blockIdx.x;        // 16384 CTAs
    int hb = bid & 3, n = (bid >> 2) & 15, c = bid >> 6;
    int h0 = hb * 33;
    const float* xp = x + (size_t)(n * 256 + c) * 16384;
#pragma unroll
    for (int i = 0; i < 6; ++i) {
        int idx = tid + i * 256;
        if (idx < 37 * 35) {
            int rr = idx / 35, c4 = idx - rr * 35;
            int ih = h0 - 2 + rr;
            float4 v = make_float4(0.f, 0.f, 0.f, 0.f);
            if (ih >= 0 && ih < 128 && c4 < 32)
                v = *reinterpret_cast<const float4*>(xp + ih * 128 + c4 * 4);
            *reinterpret_cast<float4*>(&s[rr * 140 + c4 * 4]) = v;
        }
    }
    // K = u u^T exactly (rank-1): u_b = column sums; row factor v = u (K.sum()=64 norm).
    float u0 = __ldg(bk + 0) + __ldg(bk + 4) + __ldg(bk + 8)  + __ldg(bk + 12);
    float u1 = __ldg(bk + 1) + __ldg(bk + 5) + __ldg(bk + 9)  + __ldg(bk + 13);
    float u2 = __ldg(bk + 2) + __ldg(bk + 6) + __ldg(bk + 10) + __ldg(bk + 14);
    float u3 = __ldg(bk + 3) + __ldg(bk + 7) + __ldg(bk + 11) + __ldg(bk + 15);
    __syncthreads();
#pragma unroll 1
    for (int t = tid; t < 561; t += 256) {          // 17 h-pairs x 33 w-quads
        int ph = t / 33, wq = t - ph * 33;
        int par = (wq >= 17) ? 1 : 0;
        int qw = par ? (wq - 17) : wq;
        int h0p = ph * 2;
        int basew = qw * 8 + par;                   // w' = basew + 2j (same parity)
        float hv[5][4];
#pragma unroll
        for (int dr = 0; dr < 5; ++dr) {
            const float* row = s + (h0p + dr) * 140;
            float xv[10];
#pragma unroll
            for (int q = 0; q < 10; ++q) {
                int iw = basew - 2 + q;
                xv[q] = (iw >= 0) ? row[iw] : 0.0f; // cols >=128 are zero-padded
            }
#pragma unroll
            for (int jj = 0; jj < 4; ++jj)
                hv[dr][jj] = u0 * xv[2 * jj] + u1 * xv[2 * jj + 1]
                           + u2 * xv[2 * jj + 2] + u3 * xv[2 * jj + 3];
        }
#pragma unroll
        for (int hh = 0; hh < 2; ++hh) {
            int hp = h0p + hh, habs = h0 + hp;
            if (hp > 32 || habs > 128) continue;
            float o[4];
#pragma unroll
            for (int jj = 0; jj < 4; ++jj)
                o[jj] = tf32r(u0 * hv[hh][jj] + u1 * hv[hh + 1][jj]
                            + u2 * hv[hh + 2][jj] + u3 * hv[hh + 3][jj]);
            size_t rowoff = (size_t)c * CSTRIDE + (size_t)n * NSTRIDE + (size_t)habs * WP;
            float* dst = g_xbs + (size_t)par * PLANE + rowoff + qw * 4;
            if (par == 0) {
                float* p2 = g_xbs + 2u * (size_t)PLANE + rowoff;   // plane2[i] = even[i+1]
                if (qw == 16) {
                    dst[0] = o[0];                  // even col 64 (w'=128)
                    p2[63] = o[0];
                } else {
                    *reinterpret_cast<float4*>(dst) = make_float4(o[0], o[1], o[2], o[3]);
#pragma unroll
                    for (int jj = 0; jj < 4; ++jj) {
                        int i2 = qw * 4 + jj - 1;
                        if (i2 >= 0) p2[i2] = o[jj];
                    }
                }
            } else {
                *reinterpret_cast<float4*>(dst) = make_float4(o[0], o[1], o[2], o[3]);
            }
        }
    }
}

// ---------------- 3. implicit GEMM 128x128, K-tile 32, 3-stage cp.async -------
#define STG_STRIDE 33792u    // 16384 (A) + 17408 (B: 32 x 136 floats)

__device__ __forceinline__ void load_stage(uint32_t sbase, int kt, int tid, int mt,
                                           int n_img, int ohbase) {
    // A: flat copy of 16KB fragment-ordered tile
    const float* asrc = g_apk + (size_t)(mt * 72 + kt) * 4096;
#pragma unroll
    for (int i = 0; i < 4; ++i)
        CP16(sbase + (uint32_t)(tid + 256 * i) * 16u, asrc + (tid + 256 * i) * 4);
    // B: 32 k-rows x 128 j, all 16B-aligned CP16 from plane kw
    int tap = kt >> 3, ct = kt & 7;
    int kh = tap / 3, kw = tap - kh * 3;
    int r = tid & 31, q = tid >> 5;                 // k-row, 16-col block
    int j0 = q * 16;
    int oh = ohbase + (j0 >> 6), ow = j0 & 63;
    const float* src = g_xbs + (size_t)kw * PLANE + (size_t)(ct * 32 + r) * CSTRIDE
                     + (size_t)n_img * NSTRIDE + (size_t)(2 * oh + kh) * WP + ow;
    uint32_t sB = sbase + 16384u + (uint32_t)(r * BPITCH + j0) * 4u;
#pragma unroll
    for (int i = 0; i < 4; ++i)
        CP16(sB + (uint32_t)(i * 16), src + i * 4);
}

__device__ __forceinline__ void mma_stage(const char* base, int lane, int wm, int wn,
                                          float acc[4][4][4]) {
    const float4* sA4 = reinterpret_cast<const float4*>(base);
    const float*  sB  = reinterpret_cast<const float*>(base + 16384);
    int r = lane & 3, gid = lane >> 2;
#pragma unroll
    for (int ks = 0; ks < 4; ++ks) {
        float4 af[4];
#pragma unroll
        for (int mi = 0; mi < 4; ++mi)
            af[mi] = sA4[(ks * 8 + wm * 4 + mi) * 32 + lane];
        float b0[4], b1[4];
#pragma unroll
        for (int ni = 0; ni < 4; ++ni) {
            int nn = wn * 32 + ni * 8 + gid;
            b0[ni] = sB[(ks * 8 + r) * BPITCH + nn];
            b1[ni] = sB[(ks * 8 + 4 + r) * BPITCH + nn];
        }
#pragma unroll
        for (int mi = 0; mi < 4; ++mi)
#pragma unroll
            for (int ni = 0; ni < 4; ++ni)
                mma8(acc[mi][ni], af[mi], b0[ni], b1[ni]);
    }
}

__global__ __launch_bounds__(256, 2) void gemm_kernel(const float* __restrict__ bias,
                                                      float* __restrict__ out) {
    extern __shared__ char smem[];
    uint32_t sbu = smem_u32(smem);
    const int tid = threadIdx.x, lane = tid & 31, wid = tid >> 5;
    const int wm = wid >> 2, wn = wid & 3;
    const int bid = blockIdx.x;                     // 2048 CTAs
    const int mt = bid & 3, nt = bid >> 2;          // 4 mt share B via L2
    const int n_img = nt >> 5, ohbase = (nt & 31) << 1;

    float acc[4][4][4];
#pragma unroll
    for (int a = 0; a < 4; ++a)
#pragma unroll
        for (int b = 0; b < 4; ++b)
#pragma unroll
            for (int q = 0; q < 4; ++q) acc[a][b][q] = 0.0f;

    load_stage(sbu, 0, tid, mt, n_img, ohbase);               CPCOMMIT();
    load_stage(sbu + STG_STRIDE, 1, tid, mt, n_img, ohbase);  CPCOMMIT();

#pragma unroll 1
    for (int kt = 0; kt < 72; ++kt) {
        CPWAIT(1);
        __syncthreads();
        if (kt + 2 < 72)
            load_stage(sbu + (uint32_t)((kt + 2) % 3) * STG_STRIDE, kt + 2,
                       tid, mt, n_img, ohbase);
        CPCOMMIT();
        mma_stage(smem + (size_t)(kt % 3) * STG_STRIDE, lane, wm, wn, acc);
    }

    // epilogue: D frag (row gid/+8, cols 2*tig,2*tig+1) -> float2 stores
#pragma unroll
    for (int mi = 0; mi < 4; ++mi) {
        int m = wm * 64 + mi * 16 + (lane >> 2);
        float blo = __ldg(bias + mt * 128 + m);
        float bhi = __ldg(bias + mt * 128 + m + 8);
#pragma unroll
        for (int ni = 0; ni < 4; ++ni) {
            int jj = wn * 32 + ni * 8 + (lane & 3) * 2;
            int oh = ohbase + (jj >> 6), ow = jj & 63;
            size_t base = (((size_t)n_img * 512 + mt * 128 + m) * 64 + oh) * 64 + ow;
            *reinterpret_cast<float2*>(out + base) =
                make_float2(acc[mi][ni][0] + blo, acc[mi][ni][1] + blo);
            *reinterpret_cast<float2*>(out + base + 8 * 4096) =
                make_float2(acc[mi][ni][2] + bhi, acc[mi][ni][3] + bhi);
        }
    }
}

// ---------------- launch ----------------
extern "C" void kernel_launch(void* const* d_in, const int* in_sizes, int n_in,
                              void* d_out, int out_size) {
    const float* x    = (const float*)d_in[0];
    const float* w    = (const float*)d_in[1];
    const float* bias = (const float*)d_in[2];
    const float* bk   = (const float*)d_in[3];
    float* out = (float*)d_out;
    (void)in_sizes; (void)n_in; (void)out_size;

    cudaFuncSetAttribute(gemm_kernel, cudaFuncAttributeMaxDynamicSharedMemorySize, 101376);

    prep_kernel<<<4608, 256>>>(w);
    blur_kernel<<<16384, 256>>>(x, bk);
    gemm_kernel<<<2048, 256, 101376>>>(bias, out);
}

// round 10
// speedup vs baseline: 1.3273x; 1.2452x over previous
#include <cuda_runtime.h>
#include <cstdint>

// x[16,256,128,128] f32, w[512,256,3,3], bias[512], blur_k[4,4] -> y[16,512,64,64]
// R10: R7 tiling + CP16 B staging that is j-contiguous per lane (coalesced, conflict-free).
#define WP       68
#define NSTRIDE  8772        // 129*68
#define CSTRIDE  140352      // 16*NSTRIDE
#define PLANE    35930112    // 256*CSTRIDE
#define BPITCH   136         // B smem row pitch (floats)

__device__ __align__(16) float g_xbs[3u * 35930112u];  // planes: even, odd, even-shift1
__device__ __align__(16) float g_apk[4 * 72 * 4096];   // weights, mma-fragment order

// ---------------- helpers ----------------
__device__ __forceinline__ uint32_t smem_u32(const void* p) {
    uint32_t a;
    asm("{ .reg .u64 t; cvta.to.shared.u64 t, %1; cvt.u32.u64 %0, t; }" : "=r"(a) : "l"(p));
    return a;
}
__device__ __forceinline__ float tf32r(float x) {
    uint32_t r; asm("cvt.rna.tf32.f32 %0, %1;" : "=r"(r) : "f"(x));
    return __uint_as_float(r);
}
#define CP16(dst, src) \
    asm volatile("cp.async.cg.shared.global [%0], [%1], 16;" :: "r"(dst), "l"(src))
#define CPCOMMIT() asm volatile("cp.async.commit_group;" ::: "memory")
#define CPWAIT(n)  asm volatile("cp.async.wait_group %0;" :: "n"(n) : "memory")

__device__ __forceinline__ void mma8(float* d, const float4& a, float b0f, float b1f) {
    const uint32_t* ai = reinterpret_cast<const uint32_t*>(&a);
    uint32_t b0 = __float_as_uint(b0f), b1 = __float_as_uint(b1f);
    asm volatile(
        "mma.sync.aligned.m16n8k8.row.col.f32.tf32.tf32.f32 "
        "{%0,%1,%2,%3}, {%4,%5,%6,%7}, {%8,%9}, {%0,%1,%2,%3};"
        : "+f"(d[0]), "+f"(d[1]), "+f"(d[2]), "+f"(d[3])
        : "r"(ai[0]), "r"(ai[1]), "r"(ai[2]), "r"(ai[3]), "r"(b0), "r"(b1));
}

// ---------------- 1. weight prep: scale + tf32-round + mma-fragment permute ----
__global__ __launch_bounds__(256) void prep_kernel(const float* __restrict__ w) {
    int idx = blockIdx.x * 256 + threadIdx.x;       // 512*2304
    if (idx >= 512 * 2304) return;
    int oc = idx / 2304, k = idx - oc * 2304;       // k = tap*256 + c
    int c = k & 255, tap = k >> 8;
    int kh = tap / 3, kw = tap - kh * 3;
    float v = tf32r(w[((oc * 256 + c) * 3 + kh) * 3 + kw] * (1.0f / 48.0f));
    int mt = oc >> 7, m = oc & 127;
    int kt = k >> 5, kl = k & 31;
    int ks = kl >> 3, kc = kl & 7;
    int chi = kc >> 2, c4 = kc & 3;
    int wm = m >> 6, mi = (m >> 4) & 3, mr = m & 15;
    int rhi = mr >> 3, gid = mr & 7;
    int lanei = gid * 4 + c4;
    int comp = chi * 2 + rhi;                       // (r,c),(r+8,c),(r,c+4),(r+8,c+4)
    g_apk[(size_t)(mt * 72 + kt) * 4096 + ((ks * 8 + wm * 4 + mi) * 32 + lanei) * 4 + comp] = v;
}

// ---------------- 2. separable blur -> 3 planes (even, odd, even-shift1) ------
__global__ __launch_bounds__(256) void blur_kernel(const float* __restrict__ x,
                                                   const float* __restrict__ bk) {
    __shared__ float s[37 * 140];
    int tid = threadIdx.x, bid = blockIdx.x;        // 16384 CTAs
    int hb = bid & 3, n = (bid >> 2) & 15, c = bid >> 6;
    int h0 = hb * 33;
    const float* xp = x + (size_t)(n * 256 + c) * 16384;
#pragma unroll
    for (int i = 0; i < 6; ++i) {
        int idx = tid + i * 256;
        if (idx < 37 * 35) {
            int rr = idx / 35, c4 = idx - rr * 35;
            int ih = h0 - 2 + rr;
            float4 v = make_float4(0.f, 0.f, 0.f, 0.f);
            if (ih >= 0 && ih < 128 && c4 < 32)
                v = *reinterpret_cast<const float4*>(xp + ih * 128 + c4 * 4);
            *reinterpret_cast<float4*>(&s[rr * 140 + c4 * 4]) = v;
        }
    }
    // K = u u^T exactly (rank-1): u_b = column sums; row factor v = u (K.sum()=64 norm).
    float u0 = __ldg(bk + 0) + __ldg(bk + 4) + __ldg(bk + 8)  + __ldg(bk + 12);
    float u1 = __ldg(bk + 1) + __ldg(bk + 5) + __ldg(bk + 9)  + __ldg(bk + 13);
    float u2 = __ldg(bk + 2) + __ldg(bk + 6) + __ldg(bk + 10) + __ldg(bk + 14);
    float u3 = __ldg(bk + 3) + __ldg(bk + 7) + __ldg(bk + 11) + __ldg(bk + 15);
    __syncthreads();
#pragma unroll 1
    for (int t = tid; t < 561; t += 256) {          // 17 h-pairs x 33 w-quads
        int ph = t / 33, wq = t - ph * 33;
        int par = (wq >= 17) ? 1 : 0;
        int qw = par ? (wq - 17) : wq;
        int h0p = ph * 2;
        int basew = qw * 8 + par;                   // w' = basew + 2j (same parity)
        float hv[5][4];
#pragma unroll
        for (int dr = 0; dr < 5; ++dr) {
            const float* row = s + (h0p + dr) * 140;
            float xv[10];
#pragma unroll
            for (int q = 0; q < 10; ++q) {
                int iw = basew - 2 + q;
                xv[q] = (iw >= 0) ? row[iw] : 0.0f; // cols >=128 are zero-padded
            }
#pragma unroll
            for (int jj = 0; jj < 4; ++jj)
                hv[dr][jj] = u0 * xv[2 * jj] + u1 * xv[2 * jj + 1]
                           + u2 * xv[2 * jj + 2] + u3 * xv[2 * jj + 3];
        }
#pragma unroll
        for (int hh = 0; hh < 2; ++hh) {
            int hp = h0p + hh, habs = h0 + hp;
            if (hp > 32 || habs > 128) continue;
            float o[4];
#pragma unroll
            for (int jj = 0; jj < 4; ++jj)
                o[jj] = tf32r(u0 * hv[hh][jj] + u1 * hv[hh + 1][jj]
                            + u2 * hv[hh + 2][jj] + u3 * hv[hh + 3][jj]);
            size_t rowoff = (size_t)c * CSTRIDE + (size_t)n * NSTRIDE + (size_t)habs * WP;
            float* dst = g_xbs + (size_t)par * PLANE + rowoff + qw * 4;
            if (par == 0) {
                float* p2 = g_xbs + 2u * (size_t)PLANE + rowoff;   // plane2[i] = even[i+1]
                if (qw == 16) {
                    dst[0] = o[0];                  // even col 64 (w'=128)
                    p2[63] = o[0];
                } else {
                    *reinterpret_cast<float4*>(dst) = make_float4(o[0], o[1], o[2], o[3]);
#pragma unroll
                    for (int jj = 0; jj < 4; ++jj) {
                        int i2 = qw * 4 + jj - 1;
                        if (i2 >= 0) p2[i2] = o[jj];
                    }
                }
            } else {
                *reinterpret_cast<float4*>(dst) = make_float4(o[0], o[1], o[2], o[3]);
            }
        }
    }
}

// ---------------- 3. implicit GEMM 128x128, K-tile 32, 3-stage cp.async -------
#define STG_STRIDE 33792u    // 16384 (A) + 17408 (B: 32 x 136 floats)

__device__ __forceinline__ void load_stage(uint32_t sbase, int kt, int tid, int mt,
                                           int n_img, int ohbase) {
    // A: flat copy of 16KB fragment-ordered tile (coalesced CP16)
    const float* asrc = g_apk + (size_t)(mt * 72 + kt) * 4096;
#pragma unroll
    for (int i = 0; i < 4; ++i)
        CP16(sbase + (uint32_t)(tid + 256 * i) * 16u, asrc + (tid + 256 * i) * 4);
    // B: 32 k-rows x 128 j. Lane covers j0=4*lane (16B along j -> coalesced),
    // warp w covers k-row r = pass*8 + w. Smem writes are 512B contiguous/warp.
    int tap = kt >> 3, ct = kt & 7;
    int kh = tap / 3, kw = tap - kh * 3;
    int lane = tid & 31, w = tid >> 5;
    int j0 = lane * 4;
    int oh = ohbase + (j0 >> 6), ow = j0 & 63;
    const float* srcb = g_xbs + (size_t)kw * PLANE + (size_t)n_img * NSTRIDE
                      + (size_t)(2 * oh + kh) * WP + ow;
    uint32_t sB = sbase + 16384u + (uint32_t)j0 * 4u;
#pragma unroll
    for (int i = 0; i < 4; ++i) {
        int r = i * 8 + w;
        CP16(sB + (uint32_t)(r * BPITCH) * 4u, srcb + (size_t)(ct * 32 + r) * CSTRIDE);
    }
}

__device__ __forceinline__ void mma_stage(const char* base, int lane, int wm, int wn,
                                          float acc[4][4][4]) {
    const float4* sA4 = reinterpret_cast<const float4*>(base);
    const float*  sB  = reinterpret_cast<const float*>(base + 16384);
    int r = lane & 3, gid = lane >> 2;
#pragma unroll
    for (int ks = 0; ks < 4; ++ks) {
        float4 af[4];
#pragma unroll
        for (int mi = 0; mi < 4; ++mi)
            af[mi] = sA4[(ks * 8 + wm * 4 + mi) * 32 + lane];
        float b0[4], b1[4];
#pragma unroll
        for (int ni = 0; ni < 4; ++ni) {
            int nn = wn * 32 + ni * 8 + gid;
            b0[ni] = sB[(ks * 8 + r) * BPITCH + nn];
            b1[ni] = sB[(ks * 8 + 4 + r) * BPITCH + nn];
        }
#pragma unroll
        for (int mi = 0; mi < 4; ++mi)
#pragma unroll
            for (int ni = 0; ni < 4; ++ni)
                mma8(acc[mi][ni], af[mi], b0[ni], b1[ni]);
    }
}

__global__ __launch_bounds__(256, 2) void gemm_kernel(const float* __restrict__ bias,
                                                      float* __restrict__ out) {
    extern __shared__ char smem[];
    uint32_t sbu = smem_u32(smem);
    const int tid = threadIdx.x, lane = tid & 31, wid = tid >> 5;
    const int wm = wid >> 2, wn = wid & 3;
    const int bid = blockIdx.x;                     // 2048 CTAs
    const int mt = bid & 3, nt = bid >> 2;          // 4 mt share B via L2
    const int n_img = nt >> 5, ohbase = (nt & 31) << 1;

    float acc[4][4][4];
#pragma unroll
    for (int a = 0; a < 4; ++a)
#pragma unroll
        for (int b = 0; b < 4; ++b)
#pragma unroll
            for (int q = 0; q < 4; ++q) acc[a][b][q] = 0.0f;

    load_stage(sbu, 0, tid, mt, n_img, ohbase);               CPCOMMIT();
    load_stage(sbu + STG_STRIDE, 1, tid, mt, n_img, ohbase);  CPCOMMIT();

#pragma unroll 1
    for (int kt = 0; kt < 72; ++kt) {
        CPWAIT(1);
        __syncthreads();
        if (kt + 2 < 72)
            load_stage(sbu + (uint32_t)((kt + 2) % 3) * STG_STRIDE, kt + 2,
                       tid, mt, n_img, ohbase);
        CPCOMMIT();
        mma_stage(smem + (size_t)(kt % 3) * STG_STRIDE, lane, wm, wn, acc);
    }

    // epilogue: D frag (row gid/+8, cols 2*tig,2*tig+1) -> float2 stores
#pragma unroll
    for (int mi = 0; mi < 4; ++mi) {
        int m = wm * 64 + mi * 16 + (lane >> 2);
        float blo = __ldg(bias + mt * 128 + m);
        float bhi = __ldg(bias + mt * 128 + m + 8);
#pragma unroll
        for (int ni = 0; ni < 4; ++ni) {
            int jj = wn * 32 + ni * 8 + (lane & 3) * 2;
            int oh = ohbase + (jj >> 6), ow = jj & 63;
            size_t base = (((size_t)n_img * 512 + mt * 128 + m) * 64 + oh) * 64 + ow;
            *reinterpret_cast<float2*>(out + base) =
                make_float2(acc[mi][ni][0] + blo, acc[mi][ni][1] + blo);
            *reinterpret_cast<float2*>(out + base + 8 * 4096) =
                make_float2(acc[mi][ni][2] + bhi, acc[mi][ni][3] + bhi);
        }
    }
}

// ---------------- launch ----------------
extern "C" void kernel_launch(void* const* d_in, const int* in_sizes, int n_in,
                              void* d_out, int out_size) {
    const float* x    = (const float*)d_in[0];
    const float* w    = (const float*)d_in[1];
    const float* bias = (const float*)d_in[2];
    const float* bk   = (const float*)d_in[3];
    float* out = (float*)d_out;
    (void)in_sizes; (void)n_in; (void)out_size;

    cudaFuncSetAttribute(gemm_kernel, cudaFuncAttributeMaxDynamicSharedMemorySize, 101376);

    prep_kernel<<<4608, 256>>>(w);
    blur_kernel<<<16384, 256>>>(x, bk);
    gemm_kernel<<<2048, 256, 101376>>>(bias, out);
}

// round 11
// speedup vs baseline: 1.3513x; 1.0181x over previous
#include <cuda_runtime.h>
#include <cstdint>

// x[16,256,128,128] f32, w[512,256,3,3], bias[512], blur_k[4,4] -> y[16,512,64,64]
// R11: R10 + ks-level register fragment double-buffering in mma_stage.
#define WP       68
#define NSTRIDE  8772        // 129*68
#define CSTRIDE  140352      // 16*NSTRIDE
#define PLANE    35930112    // 256*CSTRIDE
#define BPITCH   136         // B smem row pitch (floats)

__device__ __align__(16) float g_xbs[3u * 35930112u];  // planes: even, odd, even-shift1
__device__ __align__(16) float g_apk[4 * 72 * 4096];   // weights, mma-fragment order

// ---------------- helpers ----------------
__device__ __forceinline__ uint32_t smem_u32(const void* p) {
    uint32_t a;
    asm("{ .reg .u64 t; cvta.to.shared.u64 t, %1; cvt.u32.u64 %0, t; }" : "=r"(a) : "l"(p));
    return a;
}
__device__ __forceinline__ float tf32r(float x) {
    uint32_t r; asm("cvt.rna.tf32.f32 %0, %1;" : "=r"(r) : "f"(x));
    return __uint_as_float(r);
}
#define CP16(dst, src) \
    asm volatile("cp.async.cg.shared.global [%0], [%1], 16;" :: "r"(dst), "l"(src))
#define CPCOMMIT() asm volatile("cp.async.commit_group;" ::: "memory")
#define CPWAIT(n)  asm volatile("cp.async.wait_group %0;" :: "n"(n) : "memory")

__device__ __forceinline__ void mma8(float* d, const float4& a, float b0f, float b1f) {
    const uint32_t* ai = reinterpret_cast<const uint32_t*>(&a);
    uint32_t b0 = __float_as_uint(b0f), b1 = __float_as_uint(b1f);
    asm volatile(
        "mma.sync.aligned.m16n8k8.row.col.f32.tf32.tf32.f32 "
        "{%0,%1,%2,%3}, {%4,%5,%6,%7}, {%8,%9}, {%0,%1,%2,%3};"
        : "+f"(d[0]), "+f"(d[1]), "+f"(d[2]), "+f"(d[3])
        : "r"(ai[0]), "r"(ai[1]), "r"(ai[2]), "r"(ai[3]), "r"(b0), "r"(b1));
}

// ---------------- 1. weight prep: scale + tf32-round + mma-fragment permute ----
__global__ __launch_bounds__(256) void prep_kernel(const float* __restrict__ w) {
    int idx = blockIdx.x * 256 + threadIdx.x;       // 512*2304
    if (idx >= 512 * 2304) return;
    int oc = idx / 2304, k = idx - oc * 2304;       // k = tap*256 + c
    int c = k & 255, tap = k >> 8;
    int kh = tap / 3, kw = tap - kh * 3;
    float v = tf32r(w[((oc * 256 + c) * 3 + kh) * 3 + kw] * (1.0f / 48.0f));
    int mt = oc >> 7, m = oc & 127;
    int kt = k >> 5, kl = k & 31;
    int ks = kl >> 3, kc = kl & 7;
    int chi = kc >> 2, c4 = kc & 3;
    int wm = m >> 6, mi = (m >> 4) & 3, mr = m & 15;
    int rhi = mr >> 3, gid = mr & 7;
    int lanei = gid * 4 + c4;
    int comp = chi * 2 + rhi;                       // (r,c),(r+8,c),(r,c+4),(r+8,c+4)
    g_apk[(size_t)(mt * 72 + kt) * 4096 + ((ks * 8 + wm * 4 + mi) * 32 + lanei) * 4 + comp] = v;
}

// ---------------- 2. separable blur -> 3 planes (even, odd, even-shift1) ------
__global__ __launch_bounds__(256) void blur_kernel(const float* __restrict__ x,
                                                   const float* __restrict__ bk) {
    __shared__ float s[37 * 140];
    int tid = threadIdx.x, bid = blockIdx.x;        // 16384 CTAs
    int hb = bid & 3, n = (bid >> 2) & 15, c = bid >> 6;
    int h0 = hb * 33;
    const float* xp = x + (size_t)(n * 256 + c) * 16384;
#pragma unroll
    for (int i = 0; i < 6; ++i) {
        int idx = tid + i * 256;
        if (idx < 37 * 35) {
            int rr = idx / 35, c4 = idx - rr * 35;
            int ih = h0 - 2 + rr;
            float4 v = make_float4(0.f, 0.f, 0.f, 0.f);
            if (ih >= 0 && ih < 128 && c4 < 32)
                v = *reinterpret_cast<const float4*>(xp + ih * 128 + c4 * 4);
            *reinterpret_cast<float4*>(&s[rr * 140 + c4 * 4]) = v;
        }
    }
    // K = u u^T exactly (rank-1): u_b = column sums; row factor v = u (K.sum()=64 norm).
    float u0 = __ldg(bk + 0) + __ldg(bk + 4) + __ldg(bk + 8)  + __ldg(bk + 12);
    float u1 = __ldg(bk + 1) + __ldg(bk + 5) + __ldg(bk + 9)  + __ldg(bk + 13);
    float u2 = __ldg(bk + 2) + __ldg(bk + 6) + __ldg(bk + 10) + __ldg(bk + 14);
    float u3 = __ldg(bk + 3) + __ldg(bk + 7) + __ldg(bk + 11) + __ldg(bk + 15);
    __syncthreads();
#pragma unroll 1
    for (int t = tid; t < 561; t += 256) {          // 17 h-pairs x 33 w-quads
        int ph = t / 33, wq = t - ph * 33;
        int par = (wq >= 17) ? 1 : 0;
        int qw = par ? (wq - 17) : wq;
        int h0p = ph * 2;
        int basew = qw * 8 + par;                   // w' = basew + 2j (same parity)
        float hv[5][4];
#pragma unroll
        for (int dr = 0; dr < 5; ++dr) {
            const float* row = s + (h0p + dr) * 140;
            float xv[10];
#pragma unroll
            for (int q = 0; q < 10; ++q) {
                int iw = basew - 2 + q;
                xv[q] = (iw >= 0) ? row[iw] : 0.0f; // cols >=128 are zero-padded
            }
#pragma unroll
            for (int jj = 0; jj < 4; ++jj)
                hv[dr][jj] = u0 * xv[2 * jj] + u1 * xv[2 * jj + 1]
                           + u2 * xv[2 * jj + 2] + u3 * xv[2 * jj + 3];
        }
#pragma unroll
        for (int hh = 0; hh < 2; ++hh) {
            int hp = h0p + hh, habs = h0 + hp;
            if (hp > 32 || habs > 128) continue;
            float o[4];
#pragma unroll
            for (int jj = 0; jj < 4; ++jj)
                o[jj] = tf32r(u0 * hv[hh][jj] + u1 * hv[hh + 1][jj]
                            + u2 * hv[hh + 2][jj] + u3 * hv[hh + 3][jj]);
            size_t rowoff = (size_t)c * CSTRIDE + (size_t)n * NSTRIDE + (size_t)habs * WP;
            float* dst = g_xbs + (size_t)par * PLANE + rowoff + qw * 4;
            if (par == 0) {
                float* p2 = g_xbs + 2u * (size_t)PLANE + rowoff;   // plane2[i] = even[i+1]
                if (qw == 16) {
                    dst[0] = o[0];                  // even col 64 (w'=128)
                    p2[63] = o[0];
                } else {
                    *reinterpret_cast<float4*>(dst) = make_float4(o[0], o[1], o[2], o[3]);
#pragma unroll
                    for (int jj = 0; jj < 4; ++jj) {
                        int i2 = qw * 4 + jj - 1;
                        if (i2 >= 0) p2[i2] = o[jj];
                    }
                }
            } else {
                *reinterpret_cast<float4*>(dst) = make_float4(o[0], o[1], o[2], o[3]);
            }
        }
    }
}

// ---------------- 3. implicit GEMM 128x128, K-tile 32, 3-stage cp.async -------
#define STG_STRIDE 33792u    // 16384 (A) + 17408 (B: 32 x 136 floats)

__device__ __forceinline__ void load_stage(uint32_t sbase, int kt, int tid, int mt,
                                           int n_img, int ohbase) {
    // A: flat copy of 16KB fragment-ordered tile (coalesced CP16)
    const float* asrc = g_apk + (size_t)(mt * 72 + kt) * 4096;
#pragma unroll
    for (int i = 0; i < 4; ++i)
        CP16(sbase + (uint32_t)(tid + 256 * i) * 16u, asrc + (tid + 256 * i) * 4);
    // B: 32 k-rows x 128 j. Lane covers j0=4*lane (16B along j -> coalesced),
    // warp w covers k-row r = pass*8 + w. Smem writes are 512B contiguous/warp.
    int tap = kt >> 3, ct = kt & 7;
    int kh = tap / 3, kw = tap - kh * 3;
    int lane = tid & 31, w = tid >> 5;
    int j0 = lane * 4;
    int oh = ohbase + (j0 >> 6), ow = j0 & 63;
    const float* srcb = g_xbs + (size_t)kw * PLANE + (size_t)n_img * NSTRIDE
                      + (size_t)(2 * oh + kh) * WP + ow;
    uint32_t sB = sbase + 16384u + (uint32_t)j0 * 4u;
#pragma unroll
    for (int i = 0; i < 4; ++i) {
        int r = i * 8 + w;
        CP16(sB + (uint32_t)(r * BPITCH) * 4u, srcb + (size_t)(ct * 32 + r) * CSTRIDE);
    }
}

__device__ __forceinline__ void mma_stage(const char* base, int lane, int wm, int wn,
                                          float acc[4][4][4]) {
    const float4* sA4 = reinterpret_cast<const float4*>(base);
    const float*  sB  = reinterpret_cast<const float*>(base + 16384);
    int r = lane & 3, gid = lane >> 2;
    float4 af[2][4];
    float  b0[2][4], b1[2][4];
    // preload ks = 0 fragments
#pragma unroll
    for (int mi = 0; mi < 4; ++mi)
        af[0][mi] = sA4[(wm * 4 + mi) * 32 + lane];
#pragma unroll
    for (int ni = 0; ni < 4; ++ni) {
        int nn = wn * 32 + ni * 8 + gid;
        b0[0][ni] = sB[r * BPITCH + nn];
        b1[0][ni] = sB[(4 + r) * BPITCH + nn];
    }
#pragma unroll
    for (int ks = 0; ks < 4; ++ks) {
        int cur = ks & 1, nxt = cur ^ 1;
        if (ks < 3) {                               // prefetch ks+1 during ks mma
#pragma unroll
            for (int mi = 0; mi < 4; ++mi)
                af[nxt][mi] = sA4[((ks + 1) * 8 + wm * 4 + mi) * 32 + lane];
#pragma unroll
            for (int ni = 0; ni < 4; ++ni) {
                int nn = wn * 32 + ni * 8 + gid;
                b0[nxt][ni] = sB[((ks + 1) * 8 + r) * BPITCH + nn];
                b1[nxt][ni] = sB[((ks + 1) * 8 + 4 + r) * BPITCH + nn];
            }
        }
#pragma unroll
        for (int mi = 0; mi < 4; ++mi)
#pragma unroll
            for (int ni = 0; ni < 4; ++ni)
                mma8(acc[mi][ni], af[cur][mi], b0[cur][ni], b1[cur][ni]);
    }
}

__global__ __launch_bounds__(256, 2) void gemm_kernel(const float* __restrict__ bias,
                                                      float* __restrict__ out) {
    extern __shared__ char smem[];
    uint32_t sbu = smem_u32(smem);
    const int tid = threadIdx.x, lane = tid & 31, wid = tid >> 5;
    const int wm = wid >> 2, wn = wid & 3;
    const int bid = blockIdx.x;                     // 2048 CTAs
    const int mt = bid & 3, nt = bid >> 2;          // 4 mt share B via L2
    const int n_img = nt >> 5, ohbase = (nt & 31) << 1;

    float acc[4][4][4];
#pragma unroll
    for (int a = 0; a < 4; ++a)
#pragma unroll
        for (int b = 0; b < 4; ++b)
#pragma unroll
            for (int q = 0; q < 4; ++q) acc[a][b][q] = 0.0f;

    load_stage(sbu, 0, tid, mt, n_img, ohbase);               CPCOMMIT();
    load_stage(sbu + STG_STRIDE, 1, tid, mt, n_img, ohbase);  CPCOMMIT();

#pragma unroll 1
    for (int kt = 0; kt < 72; ++kt) {
        CPWAIT(1);
        __syncthreads();
        if (kt + 2 < 72)
            load_stage(sbu + (uint32_t)((kt + 2) % 3) * STG_STRIDE, kt + 2,
                       tid, mt, n_img, ohbase);
        CPCOMMIT();
        mma_stage(smem + (size_t)(kt % 3) * STG_STRIDE, lane, wm, wn, acc);
    }

    // epilogue: D frag (row gid/+8, cols 2*tig,2*tig+1) -> float2 stores
#pragma unroll
    for (int mi = 0; mi < 4; ++mi) {
        int m = wm * 64 + mi * 16 + (lane >> 2);
        float blo = __ldg(bias + mt * 128 + m);
        float bhi = __ldg(bias + mt * 128 + m + 8);
#pragma unroll
        for (int ni = 0; ni < 4; ++ni) {
            int jj = wn * 32 + ni * 8 + (lane & 3) * 2;
            int oh = ohbase + (jj >> 6), ow = jj & 63;
            size_t base = (((size_t)n_img * 512 + mt * 128 + m) * 64 + oh) * 64 + ow;
            *reinterpret_cast<float2*>(out + base) =
                make_float2(acc[mi][ni][0] + blo, acc[mi][ni][1] + blo);
            *reinterpret_cast<float2*>(out + base + 8 * 4096) =
                make_float2(acc[mi][ni][2] + bhi, acc[mi][ni][3] + bhi);
        }
    }
}

// ---------------- launch ----------------
extern "C" void kernel_launch(void* const* d_in, const int* in_sizes, int n_in,
                              void* d_out, int out_size) {
    const float* x    = (const float*)d_in[0];
    const float* w    = (const float*)d_in[1];
    const float* bias = (const float*)d_in[2];
    const float* bk   = (const float*)d_in[3];
    float* out = (float*)d_out;
    (void)in_sizes; (void)n_in; (void)out_size;

    cudaFuncSetAttribute(gemm_kernel, cudaFuncAttributeMaxDynamicSharedMemorySize, 101376);

    prep_kernel<<<4608, 256>>>(w);
    blur_kernel<<<16384, 256>>>(x, bk);
    gemm_kernel<<<2048, 256, 101376>>>(bias, out);
}